// round 13
// baseline (speedup 1.0000x reference)
#include <cuda_runtime.h>
#include <cuda_bf16.h>
#include <cuda_fp16.h>
#include <cstdint>

// ===================== Problem constants =====================
#define TOKENS   8192
#define IN_F     2048
#define OUT_F    8192
#define BM 128
#define BN 128
#define BK 64                  // fp16 elems per K-chunk
#define NCHUNK (IN_F / BK)     // 32
#define NTILES  ((OUT_F / BN) * (TOKENS / BM))   // 4096
#define STAGES 3
// Tiled global layout, PRE-SWIZZLED: tile (b, kc) = 128 rows x 64 halfs (128B pitch).
// Within each 128B row, 16B chunk c lives at position c ^ (row & 7).
#define TILE_H  (128 * 64)     // halfs per tile (8192)
#define TILE_B  (128 * 128)    // bytes per tile (16384)
#define STG_SZ  (2 * TILE_B)   // A tile + B tile per stage (32768)
#define SA_OFF  0
#define SB_OFF  TILE_B
#define SM_HDR  128            // mbarriers live in [0, 128)
#define NTHREADS 128           // 4 warps, warp grid 2x2, warp tile 64x64

// H is ~2e-6 (fp16 subnormal range) -> scale by 2^18, undo in epilogue.
#define H_SCALE   262144.0f
#define H_INVSCALE 3.814697265625e-06f

// ===================== Device scratch (no allocs allowed) =====================
// Tile-major: [b][kc][row][swizzled 16B chunks]
__device__ __align__(256) __half g_A[(size_t)(TOKENS / 128) * NCHUNK * TILE_H];
__device__ __align__(256) __half g_B[(size_t)(OUT_F / 128) * NCHUNK * TILE_H];

// ===================== Helpers (base-target PTX: sm_80/sm_90 era) =====================
__device__ __forceinline__ uint32_t smem_u32(const void* p) {
    uint32_t a;
    asm("{ .reg .u64 t; cvta.to.shared.u64 t, %1; cvt.u32.u64 %0, t; }" : "=r"(a) : "l"(p));
    return a;
}
__device__ __forceinline__ void ldsm_x4(uint32_t* r, uint32_t addr) {
    asm volatile("ldmatrix.sync.aligned.m8n8.x4.shared.b16 {%0,%1,%2,%3}, [%4];"
                 : "=r"(r[0]), "=r"(r[1]), "=r"(r[2]), "=r"(r[3]) : "r"(addr));
}
__device__ __forceinline__ void mma16816(float* c, const uint32_t* a, const uint32_t* b) {
    asm volatile(
        "mma.sync.aligned.m16n8k16.row.col.f32.f16.f16.f32 "
        "{%0,%1,%2,%3}, {%4,%5,%6,%7}, {%8,%9}, {%0,%1,%2,%3};"
        : "+f"(c[0]), "+f"(c[1]), "+f"(c[2]), "+f"(c[3])
        : "r"(a[0]), "r"(a[1]), "r"(a[2]), "r"(a[3]), "r"(b[0]), "r"(b[1]));
}
// Bulk async copy global->shared with mbarrier transaction accounting (sm_90 base)
__device__ __forceinline__ void bulk_cp(uint32_t dst, const void* src, uint32_t bytes,
                                        uint32_t mbar) {
    asm volatile(
        "cp.async.bulk.shared::cluster.global.mbarrier::complete_tx::bytes [%0], [%1], %2, [%3];"
        :: "r"(dst), "l"(src), "r"(bytes), "r"(mbar) : "memory");
}
__device__ __forceinline__ void st_cs_f2(float* p, float2 v) {
    asm volatile("st.global.cs.v2.f32 [%0], {%1, %2};" :: "l"(p), "f"(v.x), "f"(v.y) : "memory");
}
#define MBAR_INIT(m, cnt) \
    asm volatile("mbarrier.init.shared.b64 [%0], %1;" :: "r"((uint32_t)(m)), "r"((uint32_t)(cnt)) : "memory")
#define MBAR_EXPECT_TX(m, bytes) \
    asm volatile("mbarrier.arrive.expect_tx.shared.b64 _, [%0], %1;" \
                 :: "r"((uint32_t)(m)), "r"((uint32_t)(bytes)) : "memory")
#define MBAR_ARRIVE(m) \
    asm volatile("mbarrier.arrive.shared.b64 _, [%0];" :: "r"((uint32_t)(m)) : "memory")
#define MBAR_WAIT_PARITY(mbar, parity) do {                                               \
    uint32_t _m = (uint32_t)(mbar);                                                       \
    uint32_t _p = (uint32_t)(parity);                                                     \
    uint32_t _done;                                                                       \
    asm volatile("{\n\t.reg .pred p;\n\t"                                                 \
        "mbarrier.try_wait.parity.acquire.cta.shared::cta.b64 p, [%1], %2;\n\t"           \
        "selp.b32 %0, 1, 0, p;\n\t}"                                                      \
        : "=r"(_done) : "r"(_m), "r"(_p) : "memory");                                     \
    if (!_done) {                                                                         \
        asm volatile("{\n\t.reg .pred P1;\n\t"                                            \
            "WL_%=:\n\t"                                                                  \
            "mbarrier.try_wait.parity.acquire.cta.shared::cta.b64 P1, [%0], %1, 0x989680;\n\t" \
            "@P1 bra.uni WD_%=;\n\t"                                                      \
            "bra.uni WL_%=;\n\t"                                                          \
            "WD_%=:\n\t}"                                                                 \
            :: "r"(_m), "r"(_p) : "memory");                                              \
    }                                                                                     \
} while (0)

// ===================== Kernel 1: x -> fp16, pre-swizzled tiled layout =====================
// One thread = 8 consecutive floats = one 16B fp16 chunk at its swizzled slot.
__global__ void split_x_kernel(const float* __restrict__ x) {
    size_t j = (size_t)blockIdx.x * blockDim.x + threadIdx.x;  // 8-float group index
    const float4* xp = reinterpret_cast<const float4*>(x) + 2 * j;
    float4 v0 = xp[0], v1 = xp[1];
    int m  = (int)(j >> 8);             // 256 groups per row (2048/8)
    int k  = ((int)j & 255) * 8;
    int bm = m >> 7, row = m & 127;
    int kc = k >> 6, col = k & 63;
    int swc = (col >> 3) ^ (row & 7);
    size_t off = ((size_t)(bm * NCHUNK + kc) * 128 + row) * 64 + swc * 8;
    union { uint4 u; __half2 h[4]; } pk;
    pk.h[0] = __halves2half2(__float2half_rn(v0.x), __float2half_rn(v0.y));
    pk.h[1] = __halves2half2(__float2half_rn(v0.z), __float2half_rn(v0.w));
    pk.h[2] = __halves2half2(__float2half_rn(v1.x), __float2half_rn(v1.y));
    pk.h[3] = __halves2half2(__float2half_rn(v1.z), __float2half_rn(v1.w));
    *reinterpret_cast<uint4*>(g_A + off) = pk.u;
}

// ===================== Kernel 2: build H^T (K-major), scaled fp16, swizzled tiles =====================
// Ht[n, k] = sum_i rule[i, a, kq] * W[i, c, p],  k = a*512 + c, n = kq*2048 + p.
// Each thread builds one 16B chunk (8 consecutive k) in registers -> uint4 store.
__global__ void build_h_kernel(const float* __restrict__ rule, const float* __restrict__ W) {
    extern __shared__ float Ws[];  // [4][64][65] padded
    __shared__ float rs[64];
    const int t = threadIdx.x;          // 256 threads
    const int p0 = blockIdx.x * 64;     // out_per dim (2048)
    const int c0 = blockIdx.y * 64;     // in_per dim (512)

    for (int idx = t; idx < 4 * 64 * 64; idx += 256) {
        int i = idx >> 12;
        int cc = (idx >> 6) & 63;
        int pp = idx & 63;
        Ws[(i * 64 + cc) * 65 + pp] =
            W[(size_t)i * 512 * 2048 + (size_t)(c0 + cc) * 2048 + (p0 + pp)];
    }
    if (t < 64) rs[t] = rule[t];
    __syncthreads();

#pragma unroll
    for (int it = 0; it < 2; it++) {
        int item = it * 256 + t;        // 0..511
        int ch = item & 7;              // 16B chunk within the 64-wide k slice
        int pp = item >> 3;             // 0..63
#pragma unroll
        for (int a = 0; a < 4; a++) {
#pragma unroll
            for (int kq = 0; kq < 4; kq++) {
                float r0 = rs[0 * 16 + a * 4 + kq];
                float r1 = rs[1 * 16 + a * 4 + kq];
                float r2 = rs[2 * 16 + a * 4 + kq];
                float r3 = rs[3 * 16 + a * 4 + kq];
                union { uint4 u; __half h[8]; } out;
#pragma unroll
                for (int e = 0; e < 8; e++) {
                    int cc = ch * 8 + e;
                    float v = r0 * Ws[(0 * 64 + cc) * 65 + pp]
                            + r1 * Ws[(1 * 64 + cc) * 65 + pp]
                            + r2 * Ws[(2 * 64 + cc) * 65 + pp]
                            + r3 * Ws[(3 * 64 + cc) * 65 + pp];
                    out.h[e] = __float2half_rn(v * H_SCALE);
                }
                int n = kq * 2048 + p0 + pp;
                int row = n & 127, bn = n >> 7;
                int kc = a * 8 + blockIdx.y;       // (a*512 + c0 + ch*8) >> 6
                int swc = ch ^ (row & 7);
                size_t off = ((size_t)(bn * NCHUNK + kc) * 128 + row) * 64 + swc * 8;
                *reinterpret_cast<uint4*>(g_B + off) = out.u;
            }
        }
    }
}

// ===================== Kernel 3: PERSISTENT fp16 mma.sync GEMM, 2 CTAs/SM =====================
// grid = 2 * SM_count persistent CTAs; each processes tiles cta, cta+G, cta+2G, ...
// The 3-slot bulk-copy ring runs over the CTA's whole chunk sequence and crosses
// tile boundaries: during tile i's epilogue, tile i+1's first chunks are already
// loading. Full/empty mbarrier handshake; no per-wave fill/drain bubbles.
__global__ void __launch_bounds__(NTHREADS, 2)
phm_gemm_kernel(float* __restrict__ y, const float* __restrict__ bias) {
    extern __shared__ char smem[];
    const uint32_t sb = smem_u32(smem);
    const int tid = threadIdx.x;
    const int wid = tid >> 5, lane = tid & 31;
    const int wm = wid >> 1, wn = wid & 1;     // 2 x 2 warp grid
    const int cta = blockIdx.x, G = gridDim.x;

    const int ntiles = (NTILES - cta + G - 1) / G;
    const int total = ntiles * NCHUNK;          // chunks in this CTA's sequence

    // chunk s -> global tile t = cta + (s>>5)*G ; kc = s & 31
    auto srcA = [&](int s) {
        int t = cta + (s >> 5) * G;
        return (const __half*)g_A + ((size_t)(t >> 6) * NCHUNK + (s & 31)) * TILE_H;
    };
    auto srcB = [&](int s) {
        int t = cta + (s >> 5) * G;
        return (const __half*)g_B + ((size_t)(t & 63) * NCHUNK + (s & 31)) * TILE_H;
    };

    // full[s] at sb + s*8 (count 1, tx); empty[s] at sb + 24 + s*8 (count 4)
    if (tid == 0) {
        MBAR_INIT(sb + 0, 1);
        MBAR_INIT(sb + 8, 1);
        MBAR_INIT(sb + 16, 1);
        MBAR_INIT(sb + 24, 4);
        MBAR_INIT(sb + 32, 4);
        MBAR_INIT(sb + 40, 4);
    }
    __syncthreads();

    // fill slots 0,1 with chunks 0,1
    if (tid == 0) {
#pragma unroll
        for (int p = 0; p < STAGES - 1; p++) {
            uint32_t mb = sb + p * 8;
            uint32_t s = sb + SM_HDR + p * STG_SZ;
            MBAR_EXPECT_TX(mb, STG_SZ);
            bulk_cp(s + SA_OFF, srcA(p), TILE_B, mb);
            bulk_cp(s + SB_OFF, srcB(p), TILE_B, mb);
        }
    }

    float acc[4][8][4];                          // warp tile 64x64
#pragma unroll
    for (int mf = 0; mf < 4; mf++)
#pragma unroll
        for (int n8 = 0; n8 < 8; n8++)
#pragma unroll
            for (int q = 0; q < 4; q++) acc[mf][n8][q] = 0.0f;

    // lane addressing for ldmatrix (tile-invariant)
    const int a_row = wm * 64 + (lane & 15);
    const int a_cpick = lane >> 4;                 // 0/1 -> k +0 / +8
    const int bg = lane >> 3;                      // 0..3
    const int b_row = wn * 64 + ((bg >> 1) << 3) + (lane & 7);
    const int b_cpick = bg & 1;

    int stg = 0, ph = 0;
    int ecyc = 0, epar = 0;                        // producer empty-parity cursor
    for (int s = 0; s < total; s++) {
        MBAR_WAIT_PARITY(sb + stg * 8, ph);        // chunk s data ready

        // producer: refill slot (s+2)%3 with chunk s+2 once consumers drained chunk s-1
        if (tid == 0 && s + STAGES - 1 < total) {
            int ns = stg + STAGES - 1; if (ns >= STAGES) ns -= STAGES;
            if (s >= 1) {
                MBAR_WAIT_PARITY(sb + 24 + ns * 8, epar);
                if (++ecyc == STAGES) { ecyc = 0; epar ^= 1; }
            }
            uint32_t mb = sb + ns * 8;
            uint32_t d = sb + SM_HDR + ns * STG_SZ;
            MBAR_EXPECT_TX(mb, STG_SZ);
            bulk_cp(d + SA_OFF, srcA(s + STAGES - 1), TILE_B, mb);
            bulk_cp(d + SB_OFF, srcB(s + STAGES - 1), TILE_B, mb);
        }

        const uint32_t sm = sb + SM_HDR + stg * STG_SZ;
#pragma unroll
        for (int ks = 0; ks < 4; ks++) {          // 4 x k16 per 64-wide chunk
            uint32_t ah[4][4];
#pragma unroll
            for (int mf = 0; mf < 4; mf++) {
                int row = a_row + mf * 16;
                int cidx = ks * 2 + a_cpick;
                uint32_t ad = sm + SA_OFF + (uint32_t)(row * 128 + ((cidx ^ (row & 7)) * 16));
                ldsm_x4(ah[mf], ad);
            }
#pragma unroll
            for (int nf2 = 0; nf2 < 4; nf2++) {
                int n = b_row + nf2 * 16;
                int cidx = ks * 2 + b_cpick;
                uint32_t bd = sm + SB_OFF + (uint32_t)(n * 128 + ((cidx ^ (n & 7)) * 16));
                uint32_t bh[4];
                ldsm_x4(bh, bd);
#pragma unroll
                for (int mf = 0; mf < 4; mf++)
#pragma unroll
                    for (int nt = 0; nt < 2; nt++)
                        mma16816(acc[mf][nf2 * 2 + nt], ah[mf], &bh[nt * 2]);
            }
        }

        if (lane == 0) MBAR_ARRIVE(sb + 24 + stg * 8);  // this warp done with slot
        if (++stg == STAGES) { stg = 0; ph ^= 1; }

        // ---- per-tile epilogue: next tile's chunks already loading in the ring ----
        if ((s & (NCHUNK - 1)) == NCHUNK - 1) {
            int t = cta + (s >> 5) * G;
            int bm = t >> 6, bn = t & 63;
            const int row0 = bm * BM + wm * 64 + (lane >> 2);
            const int col0 = bn * BN + wn * 64 + (lane & 3) * 2;
#pragma unroll
            for (int mf = 0; mf < 4; mf++) {
#pragma unroll
                for (int n8 = 0; n8 < 8; n8++) {
                    int col = col0 + n8 * 8;
                    float b0 = bias[col], b1 = bias[col + 1];
                    float* p0 = y + (size_t)(row0 + mf * 16) * OUT_F + col;
                    float* p1 = y + (size_t)(row0 + mf * 16 + 8) * OUT_F + col;
                    st_cs_f2(p0, make_float2(fmaf(acc[mf][n8][0], H_INVSCALE, b0),
                                             fmaf(acc[mf][n8][1], H_INVSCALE, b1)));
                    st_cs_f2(p1, make_float2(fmaf(acc[mf][n8][2], H_INVSCALE, b0),
                                             fmaf(acc[mf][n8][3], H_INVSCALE, b1)));
                    acc[mf][n8][0] = 0.0f; acc[mf][n8][1] = 0.0f;
                    acc[mf][n8][2] = 0.0f; acc[mf][n8][3] = 0.0f;
                }
            }
        }
    }
}

// ===================== Launch =====================
extern "C" void kernel_launch(void* const* d_in, const int* in_sizes, int n_in,
                              void* d_out, int out_size) {
    const float* x    = (const float*)d_in[0];   // (8192, 2048)
    const float* rule = (const float*)d_in[1];   // (4, 4, 4)
    const float* W    = (const float*)d_in[2];   // (4, 512, 2048)
    const float* b    = (const float*)d_in[3];   // (8192,)
    float* y          = (float*)d_out;           // (8192, 8192)

    int nsm = 0;
    cudaDeviceGetAttribute(&nsm, cudaDevAttrMultiProcessorCount, 0);
    if (nsm <= 0) nsm = 148;
    const int ncta = 2 * nsm;                    // persistent: exactly 2 CTAs per SM

    cudaFuncSetAttribute(build_h_kernel, cudaFuncAttributeMaxDynamicSharedMemorySize,
                         4 * 64 * 65 * 4);
    cudaFuncSetAttribute(phm_gemm_kernel, cudaFuncAttributeMaxDynamicSharedMemorySize,
                         SM_HDR + STAGES * STG_SZ);

    // 1) x -> fp16 (pre-swizzled tiles)
    split_x_kernel<<<8192, 256>>>(x);
    // 2) H^T (K-major), scaled by 2^18, fp16 (pre-swizzled tiles)
    build_h_kernel<<<dim3(2048 / 64, 512 / 64), 256, 4 * 64 * 65 * 4>>>(rule, W);
    // 3) GEMM: y = x @ H + b, persistent CTAs, cross-tile bulk-copy ring
    phm_gemm_kernel<<<ncta, NTHREADS, SM_HDR + STAGES * STG_SZ>>>(y, b);
}

// round 14
// speedup vs baseline: 1.0537x; 1.0537x over previous
#include <cuda_runtime.h>
#include <cuda_bf16.h>
#include <cuda_fp16.h>
#include <cstdint>

// ===================== Problem constants =====================
#define TOKENS   8192
#define IN_F     2048
#define OUT_F    8192
#define BM 128
#define BN 128
#define BK 64                  // fp16 elems per K-chunk
#define NCHUNK (IN_F / BK)     // 32
#define STAGES 3
// Tiled global layout, PRE-SWIZZLED: tile (b, kc) = 128 rows x 64 halfs (128B pitch).
// Within each 128B row, 16B chunk c lives at position c ^ (row & 7).
#define TILE_H  (128 * 64)     // halfs per tile (8192)
#define TILE_B  (128 * 128)    // bytes per tile (16384)
#define STG_SZ  (2 * TILE_B)   // A tile + B tile per stage (32768)
#define SA_OFF  0
#define SB_OFF  TILE_B
#define SM_HDR  128            // mbarriers live in [0, 128)
#define NTHREADS 128           // 4 warps, warp grid 2x2, warp tile 64x64

// H is ~2e-6 (fp16 subnormal range) -> scale by 2^18, undo in epilogue.
#define H_SCALE   262144.0f
#define H_INVSCALE 3.814697265625e-06f

// ===================== Device scratch (no allocs allowed) =====================
// Tile-major: [b][kc][row][swizzled 16B chunks]
__device__ __align__(256) __half g_A[(size_t)(TOKENS / 128) * NCHUNK * TILE_H];
__device__ __align__(256) __half g_B[(size_t)(OUT_F / 128) * NCHUNK * TILE_H];

// ===================== Helpers (base-target PTX: sm_80/sm_90 era) =====================
__device__ __forceinline__ uint32_t smem_u32(const void* p) {
    uint32_t a;
    asm("{ .reg .u64 t; cvta.to.shared.u64 t, %1; cvt.u32.u64 %0, t; }" : "=r"(a) : "l"(p));
    return a;
}
__device__ __forceinline__ void ldsm_x4(uint32_t* r, uint32_t addr) {
    asm volatile("ldmatrix.sync.aligned.m8n8.x4.shared.b16 {%0,%1,%2,%3}, [%4];"
                 : "=r"(r[0]), "=r"(r[1]), "=r"(r[2]), "=r"(r[3]) : "r"(addr));
}
__device__ __forceinline__ void mma16816(float* c, const uint32_t* a, const uint32_t* b) {
    asm volatile(
        "mma.sync.aligned.m16n8k16.row.col.f32.f16.f16.f32 "
        "{%0,%1,%2,%3}, {%4,%5,%6,%7}, {%8,%9}, {%0,%1,%2,%3};"
        : "+f"(c[0]), "+f"(c[1]), "+f"(c[2]), "+f"(c[3])
        : "r"(a[0]), "r"(a[1]), "r"(a[2]), "r"(a[3]), "r"(b[0]), "r"(b[1]));
}
// Bulk async copy global->shared with mbarrier transaction accounting (sm_90 base)
__device__ __forceinline__ void bulk_cp(uint32_t dst, const void* src, uint32_t bytes,
                                        uint32_t mbar) {
    asm volatile(
        "cp.async.bulk.shared::cluster.global.mbarrier::complete_tx::bytes [%0], [%1], %2, [%3];"
        :: "r"(dst), "l"(src), "r"(bytes), "r"(mbar) : "memory");
}
__device__ __forceinline__ void st_cs_f2(float* p, float2 v) {
    asm volatile("st.global.cs.v2.f32 [%0], {%1, %2};" :: "l"(p), "f"(v.x), "f"(v.y) : "memory");
}
#define MBAR_INIT(m, cnt) \
    asm volatile("mbarrier.init.shared.b64 [%0], %1;" :: "r"((uint32_t)(m)), "r"((uint32_t)(cnt)) : "memory")
#define MBAR_EXPECT_TX(m, bytes) \
    asm volatile("mbarrier.arrive.expect_tx.shared.b64 _, [%0], %1;" \
                 :: "r"((uint32_t)(m)), "r"((uint32_t)(bytes)) : "memory")
#define MBAR_ARRIVE(m) \
    asm volatile("mbarrier.arrive.shared.b64 _, [%0];" :: "r"((uint32_t)(m)) : "memory")
#define MBAR_WAIT_PARITY(mbar, parity) do {                                               \
    uint32_t _m = (uint32_t)(mbar);                                                       \
    uint32_t _p = (uint32_t)(parity);                                                     \
    uint32_t _done;                                                                       \
    asm volatile("{\n\t.reg .pred p;\n\t"                                                 \
        "mbarrier.try_wait.parity.acquire.cta.shared::cta.b64 p, [%1], %2;\n\t"           \
        "selp.b32 %0, 1, 0, p;\n\t}"                                                      \
        : "=r"(_done) : "r"(_m), "r"(_p) : "memory");                                     \
    if (!_done) {                                                                         \
        asm volatile("{\n\t.reg .pred P1;\n\t"                                            \
            "WL_%=:\n\t"                                                                  \
            "mbarrier.try_wait.parity.acquire.cta.shared::cta.b64 P1, [%0], %1, 0x989680;\n\t" \
            "@P1 bra.uni WD_%=;\n\t"                                                      \
            "bra.uni WL_%=;\n\t"                                                          \
            "WD_%=:\n\t}"                                                                 \
            :: "r"(_m), "r"(_p) : "memory");                                              \
    }                                                                                     \
} while (0)

// ===================== Kernel 1: x -> fp16, pre-swizzled tiled layout =====================
// One thread = 8 consecutive floats = one 16B fp16 chunk at its swizzled slot.
__global__ void split_x_kernel(const float* __restrict__ x) {
    size_t j = (size_t)blockIdx.x * blockDim.x + threadIdx.x;  // 8-float group index
    const float4* xp = reinterpret_cast<const float4*>(x) + 2 * j;
    float4 v0 = xp[0], v1 = xp[1];
    int m  = (int)(j >> 8);             // 256 groups per row (2048/8)
    int k  = ((int)j & 255) * 8;
    int bm = m >> 7, row = m & 127;
    int kc = k >> 6, col = k & 63;
    int swc = (col >> 3) ^ (row & 7);
    size_t off = ((size_t)(bm * NCHUNK + kc) * 128 + row) * 64 + swc * 8;
    union { uint4 u; __half2 h[4]; } pk;
    pk.h[0] = __halves2half2(__float2half_rn(v0.x), __float2half_rn(v0.y));
    pk.h[1] = __halves2half2(__float2half_rn(v0.z), __float2half_rn(v0.w));
    pk.h[2] = __halves2half2(__float2half_rn(v1.x), __float2half_rn(v1.y));
    pk.h[3] = __halves2half2(__float2half_rn(v1.z), __float2half_rn(v1.w));
    *reinterpret_cast<uint4*>(g_A + off) = pk.u;
}

// ===================== Kernel 2: build H^T (K-major), scaled fp16, swizzled tiles =====================
// Ht[n, k] = sum_i rule[i, a, kq] * W[i, c, p],  k = a*512 + c, n = kq*2048 + p.
// Each thread builds one 16B chunk (8 consecutive k) in registers -> uint4 store.
__global__ void build_h_kernel(const float* __restrict__ rule, const float* __restrict__ W) {
    extern __shared__ float Ws[];  // [4][64][65] padded
    __shared__ float rs[64];
    const int t = threadIdx.x;          // 256 threads
    const int p0 = blockIdx.x * 64;     // out_per dim (2048)
    const int c0 = blockIdx.y * 64;     // in_per dim (512)

    for (int idx = t; idx < 4 * 64 * 64; idx += 256) {
        int i = idx >> 12;
        int cc = (idx >> 6) & 63;
        int pp = idx & 63;
        Ws[(i * 64 + cc) * 65 + pp] =
            W[(size_t)i * 512 * 2048 + (size_t)(c0 + cc) * 2048 + (p0 + pp)];
    }
    if (t < 64) rs[t] = rule[t];
    __syncthreads();

#pragma unroll
    for (int it = 0; it < 2; it++) {
        int item = it * 256 + t;        // 0..511
        int ch = item & 7;              // 16B chunk within the 64-wide k slice
        int pp = item >> 3;             // 0..63
#pragma unroll
        for (int a = 0; a < 4; a++) {
#pragma unroll
            for (int kq = 0; kq < 4; kq++) {
                float r0 = rs[0 * 16 + a * 4 + kq];
                float r1 = rs[1 * 16 + a * 4 + kq];
                float r2 = rs[2 * 16 + a * 4 + kq];
                float r3 = rs[3 * 16 + a * 4 + kq];
                union { uint4 u; __half h[8]; } out;
#pragma unroll
                for (int e = 0; e < 8; e++) {
                    int cc = ch * 8 + e;
                    float v = r0 * Ws[(0 * 64 + cc) * 65 + pp]
                            + r1 * Ws[(1 * 64 + cc) * 65 + pp]
                            + r2 * Ws[(2 * 64 + cc) * 65 + pp]
                            + r3 * Ws[(3 * 64 + cc) * 65 + pp];
                    out.h[e] = __float2half_rn(v * H_SCALE);
                }
                int n = kq * 2048 + p0 + pp;
                int row = n & 127, bn = n >> 7;
                int kc = a * 8 + blockIdx.y;       // (a*512 + c0 + ch*8) >> 6
                int swc = ch ^ (row & 7);
                size_t off = ((size_t)(bn * NCHUNK + kc) * 128 + row) * 64 + swc * 8;
                *reinterpret_cast<uint4*>(g_B + off) = out.u;
            }
        }
    }
}

// ===================== Kernel 3: fp16 mma.sync GEMM, bulk-copy pipeline, 2 CTAs/SM =====================
// 128x128 CTA tile, 4 warps (64x64 warp tiles), wave-scheduled grid (proven best).
// 3-stage ring, ONE 16KB cp.async.bulk per tile per chunk. Tweaks this round:
//  - prefetch-first: producer issues the refill for chunk kc+2 BEFORE waiting on
//    chunk kc, so a stalled pipeline still keeps 3 bulk pairs in flight;
//  - early empty-arrive: consumers release the slot right after the chunk's last
//    ldmatrix (data in registers), before the final MMA batch.
__global__ void __launch_bounds__(NTHREADS, 2)
phm_gemm_kernel(float* __restrict__ y, const float* __restrict__ bias) {
    extern __shared__ char smem[];
    const uint32_t sb = smem_u32(smem);
    const int tid = threadIdx.x;
    const int wid = tid >> 5, lane = tid & 31;
    const int wm = wid >> 1, wn = wid & 1;     // 2 x 2 warp grid
    const int bn = blockIdx.x, bm = blockIdx.y;

    const __half* At = g_A + (size_t)bm * NCHUNK * TILE_H;
    const __half* Bt = g_B + (size_t)bn * NCHUNK * TILE_H;

    // full[s] at sb + s*8 (count 1, tx); empty[s] at sb + 24 + s*8 (count 4)
    if (tid == 0) {
        MBAR_INIT(sb + 0, 1);
        MBAR_INIT(sb + 8, 1);
        MBAR_INIT(sb + 16, 1);
        MBAR_INIT(sb + 24, 4);
        MBAR_INIT(sb + 32, 4);
        MBAR_INIT(sb + 40, 4);
    }
    __syncthreads();

    // prologue: fill slots 0,1 with chunks 0,1
    if (tid == 0) {
#pragma unroll
        for (int p = 0; p < STAGES - 1; p++) {
            uint32_t mb = sb + p * 8;
            uint32_t s = sb + SM_HDR + p * STG_SZ;
            MBAR_EXPECT_TX(mb, STG_SZ);
            bulk_cp(s + SA_OFF, At + (size_t)p * TILE_H, TILE_B, mb);
            bulk_cp(s + SB_OFF, Bt + (size_t)p * TILE_H, TILE_B, mb);
        }
    }

    float acc[4][8][4];                          // warp tile 64x64
#pragma unroll
    for (int mf = 0; mf < 4; mf++)
#pragma unroll
        for (int n8 = 0; n8 < 8; n8++)
#pragma unroll
            for (int q = 0; q < 4; q++) acc[mf][n8][q] = 0.0f;

    // lane addressing for ldmatrix
    const int a_row = wm * 64 + (lane & 15);
    const int a_cpick = lane >> 4;                 // 0/1 -> k +0 / +8
    const int bg = lane >> 3;                      // 0..3
    const int b_row = wn * 64 + ((bg >> 1) << 3) + (lane & 7);
    const int b_cpick = bg & 1;

    int stg = 0, ph = 0;
    int ecyc = 0, epar = 0;                        // producer empty-parity cursor
    for (int kc = 0; kc < NCHUNK; kc++) {
        // ---- producer prefetch FIRST (independent of chunk kc's readiness) ----
        if (tid == 0 && kc + STAGES - 1 < NCHUNK) {
            int ns = stg + STAGES - 1; if (ns >= STAGES) ns -= STAGES;
            if (kc >= 1) {                          // slot held chunk kc-1 before
                MBAR_WAIT_PARITY(sb + 24 + ns * 8, epar);
                if (++ecyc == STAGES) { ecyc = 0; epar ^= 1; }
            }
            uint32_t mb = sb + ns * 8;
            uint32_t d = sb + SM_HDR + ns * STG_SZ;
            MBAR_EXPECT_TX(mb, STG_SZ);
            bulk_cp(d + SA_OFF, At + (size_t)(kc + STAGES - 1) * TILE_H, TILE_B, mb);
            bulk_cp(d + SB_OFF, Bt + (size_t)(kc + STAGES - 1) * TILE_H, TILE_B, mb);
        }

        MBAR_WAIT_PARITY(sb + stg * 8, ph);        // chunk kc data ready

        const uint32_t s = sb + SM_HDR + stg * STG_SZ;
#pragma unroll
        for (int ks = 0; ks < 4; ks++) {          // 4 x k16 per 64-wide chunk
            uint32_t ah[4][4];
#pragma unroll
            for (int mf = 0; mf < 4; mf++) {
                int row = a_row + mf * 16;
                int cidx = ks * 2 + a_cpick;
                uint32_t ad = s + SA_OFF + (uint32_t)(row * 128 + ((cidx ^ (row & 7)) * 16));
                ldsm_x4(ah[mf], ad);
            }
#pragma unroll
            for (int nf2 = 0; nf2 < 4; nf2++) {
                int n = b_row + nf2 * 16;
                int cidx = ks * 2 + b_cpick;
                uint32_t bd = s + SB_OFF + (uint32_t)(n * 128 + ((cidx ^ (n & 7)) * 16));
                uint32_t bh[4];
                ldsm_x4(bh, bd);
                // Early slot release: after the chunk's LAST ldmatrix, before the
                // final MMA batch (all slot data now lives in registers).
                if (ks == 3 && nf2 == 3 && lane == 0)
                    MBAR_ARRIVE(sb + 24 + stg * 8);
#pragma unroll
                for (int mf = 0; mf < 4; mf++)
#pragma unroll
                    for (int nt = 0; nt < 2; nt++)
                        mma16816(acc[mf][nf2 * 2 + nt], ah[mf], &bh[nt * 2]);
            }
        }
        if (++stg == STAGES) { stg = 0; ph ^= 1; }
    }

    // ---- epilogue: acc * 2^-18 + bias -> y, streaming float2 stores ----
    const int row0 = bm * BM + wm * 64 + (lane >> 2);
    const int col0 = bn * BN + wn * 64 + (lane & 3) * 2;
#pragma unroll
    for (int mf = 0; mf < 4; mf++) {
#pragma unroll
        for (int n8 = 0; n8 < 8; n8++) {
            int col = col0 + n8 * 8;
            float b0 = bias[col], b1 = bias[col + 1];
            float* p0 = y + (size_t)(row0 + mf * 16) * OUT_F + col;
            float* p1 = y + (size_t)(row0 + mf * 16 + 8) * OUT_F + col;
            st_cs_f2(p0, make_float2(fmaf(acc[mf][n8][0], H_INVSCALE, b0),
                                     fmaf(acc[mf][n8][1], H_INVSCALE, b1)));
            st_cs_f2(p1, make_float2(fmaf(acc[mf][n8][2], H_INVSCALE, b0),
                                     fmaf(acc[mf][n8][3], H_INVSCALE, b1)));
        }
    }
}

// ===================== Launch =====================
extern "C" void kernel_launch(void* const* d_in, const int* in_sizes, int n_in,
                              void* d_out, int out_size) {
    const float* x    = (const float*)d_in[0];   // (8192, 2048)
    const float* rule = (const float*)d_in[1];   // (4, 4, 4)
    const float* W    = (const float*)d_in[2];   // (4, 512, 2048)
    const float* b    = (const float*)d_in[3];   // (8192,)
    float* y          = (float*)d_out;           // (8192, 8192)

    cudaFuncSetAttribute(build_h_kernel, cudaFuncAttributeMaxDynamicSharedMemorySize,
                         4 * 64 * 65 * 4);
    cudaFuncSetAttribute(phm_gemm_kernel, cudaFuncAttributeMaxDynamicSharedMemorySize,
                         SM_HDR + STAGES * STG_SZ);

    // 1) x -> fp16 (pre-swizzled tiles)
    split_x_kernel<<<8192, 256>>>(x);
    // 2) H^T (K-major), scaled by 2^18, fp16 (pre-swizzled tiles)
    build_h_kernel<<<dim3(2048 / 64, 512 / 64), 256, 4 * 64 * 65 * 4>>>(rule, W);
    // 3) GEMM: y = x @ H + b, wave-scheduled, prefetch-first ring, 2 CTAs/SM
    phm_gemm_kernel<<<dim3(OUT_F / BN, TOKENS / BM), NTHREADS,
                      SM_HDR + STAGES * STG_SZ>>>(y, b);
}